// round 16
// baseline (speedup 1.0000x reference)
#include <cuda_runtime.h>
#include <cuda_bf16.h>
#include <math.h>
#include <cstdint>

#define TTOT 131072
#define SCALE 0.17677669529663687f
#define GN_N 1048576.0f

__device__ __forceinline__ void mma16816(float* d, const uint32_t* a, const uint32_t* b) {
    asm volatile("mma.sync.aligned.m16n8k16.row.col.f32.bf16.bf16.f32 "
        "{%0,%1,%2,%3}, {%4,%5,%6,%7}, {%8,%9}, {%0,%1,%2,%3};"
        : "+f"(d[0]), "+f"(d[1]), "+f"(d[2]), "+f"(d[3])
        : "r"(a[0]), "r"(a[1]), "r"(a[2]), "r"(a[3]), "r"(b[0]), "r"(b[1]));
}
__device__ __forceinline__ void ldsm4(uint32_t& r0, uint32_t& r1, uint32_t& r2, uint32_t& r3,
                                      uint32_t addr) {
    asm volatile("ldmatrix.sync.aligned.m8n8.x4.shared.b16 {%0,%1,%2,%3}, [%4];"
                 : "=r"(r0), "=r"(r1), "=r"(r2), "=r"(r3) : "r"(addr));
}
__device__ __forceinline__ uint32_t smem_u32(const void* p) {
    uint32_t a;
    asm("{ .reg .u64 t; cvta.to.shared.u64 t, %1; cvt.u32.u64 %0, t; }" : "=r"(a) : "l"(p));
    return a;
}
__device__ __forceinline__ float bf2f(__nv_bfloat16 h) { return __bfloat162float(h); }

#define CP_A16(d, s) asm volatile("cp.async.cg.shared.global [%0], [%1], 16;" :: "r"(d), "l"(s) : "memory")
#define CP_A16Z(d, s, sz) asm volatile("cp.async.cg.shared.global [%0], [%1], 16, %2;" :: "r"(d), "l"(s), "r"(sz) : "memory")
#define CP_COMMIT()  asm volatile("cp.async.commit_group;" ::: "memory")
#define CP_WAIT1()   asm volatile("cp.async.wait_group 1;" ::: "memory")

// ---------------- scratch ----------------
__device__ __nv_bfloat16 g_xh [(size_t)TTOT*256];
__device__ __nv_bfloat16 g_xl [(size_t)TTOT*256];
__device__ __nv_bfloat16 g_kh [(size_t)TTOT*256];
__device__ __nv_bfloat16 g_kl [(size_t)TTOT*256];
__device__ __nv_bfloat16 g_qah[(size_t)TTOT*256];
__device__ __nv_bfloat16 g_qal[(size_t)TTOT*256];
__device__ __nv_bfloat16 g_vh [(size_t)TTOT*256];
__device__ __nv_bfloat16 g_vl [(size_t)TTOT*256];
__device__ __nv_bfloat16 g_atth[(size_t)TTOT*256];
__device__ __nv_bfloat16 g_attl[(size_t)TTOT*256];
__device__ __nv_bfloat16 g_uphi[(size_t)TTOT*64];
__device__ __nv_bfloat16 g_uplo[(size_t)TTOT*64];
__device__ __nv_bfloat16 g_ulsh[(size_t)TTOT*64];
__device__ __nv_bfloat16 g_ulsl[(size_t)TTOT*64];
__device__ float g_q  [(size_t)TTOT*256];
__device__ float g_y1 [(size_t)TTOT*256];
__device__ float g_y2 [(size_t)TTOT*192];
__device__ __nv_bfloat16 g_bqh  [768*256];
__device__ __nv_bfloat16 g_bql  [768*256];
__device__ __nv_bfloat16 g_bouth[256*256];
__device__ __nv_bfloat16 g_boutl[256*256];
__device__ __nv_bfloat16 g_bsqh [128*256];
__device__ __nv_bfloat16 g_bsql [128*256];
__device__ __nv_bfloat16 g_bp2h [256*64];
__device__ __nv_bfloat16 g_bp2l [256*64];
__device__ __nv_bfloat16 g_bcvh [2*128*352];
__device__ __nv_bfloat16 g_bcvl [2*128*352];
__device__ float g_gnstats[2*16*2];
__device__ float g_pool[2*512];
__device__ float g_misc[4];

// ---------------- small utilities ----------------
__global__ void zero_small() {
    int i = blockIdx.x*256 + threadIdx.x;
    if (i < 1024) g_pool[i] = 0.f;
    if (i < 64)   g_gnstats[i] = 0.f;
}
__global__ void sum_gnw(const float* __restrict__ gn_w) {
    __shared__ float sh[256];
    sh[threadIdx.x] = gn_w[threadIdx.x];
    __syncthreads();
    for (int st = 128; st > 0; st >>= 1) {
        if (threadIdx.x < st) sh[threadIdx.x] += sh[threadIdx.x + st];
        __syncthreads();
    }
    if (threadIdx.x == 0) g_misc[0] = sh[0];
}
__global__ void prep_bw(const float* __restrict__ w,
                        __nv_bfloat16* __restrict__ dh, __nv_bfloat16* __restrict__ dl, int total) {
    int i = blockIdx.x*256 + threadIdx.x;
    if (i >= total) return;
    float v = w[i];
    __nv_bfloat16 h = __float2bfloat16(v);
    dh[i] = h;
    dl[i] = __float2bfloat16(v - bf2f(h));
}
__global__ void prep_bsq(const float* __restrict__ sq1, const float* __restrict__ sq2) {
    int i = blockIdx.x*256 + threadIdx.x;
    if (i >= 128*256) return;
    int n = i >> 8, k = i & 255;
    float w = 0.f;
    if (n < 64)  { if (k < 128)  w = sq1[n*128 + k]; }
    else         { if (k >= 128) w = sq2[(n-64)*128 + (k-128)]; }
    __nv_bfloat16 h = __float2bfloat16(w);
    g_bsqh[i] = h;
    g_bsql[i] = __float2bfloat16(w - bf2f(h));
}
__global__ void prep_bp2(const float* __restrict__ pwc2) {
    int i = blockIdx.x*256 + threadIdx.x;
    if (i >= 256*64) return;
    int n = i >> 6, k = i & 63;
    float w = (n < 192) ? pwc2[n*64 + k] : 0.f;
    __nv_bfloat16 h = __float2bfloat16(w);
    g_bp2h[i] = h;
    g_bp2l[i] = __float2bfloat16(w - bf2f(h));
}
__global__ void prep_bcv(const float* __restrict__ gwc, const float* __restrict__ pwc1) {
    int i = blockIdx.x*256 + threadIdx.x;
    if (i >= 2*128*352) return;
    int z = i / (128*352), r = i % (128*352);
    int n = r / 352, k = r % 352;
    int c = z*128 + n;
    float w = (k < 288) ? gwc[c*288 + (k & 31)*9 + (k >> 5)] : pwc1[c*64 + (k - 288)];
    __nv_bfloat16 h = __float2bfloat16(w);
    g_bcvh[i] = h;
    g_bcvl[i] = __float2bfloat16(w - bf2f(h));
}

// ---------------- roll + split x ----------------
__global__ __launch_bounds__(256) void xsplit(const float* __restrict__ x) {
    __shared__ float s[256][33];
    int bid = blockIdx.x;
    int b = bid >> 11, rem = bid & 2047;
    int hr = rem >> 3, w0 = (rem & 7) << 5;
    int tid = threadIdx.x, wid = tid >> 5, lane = tid & 31;
    int hs = ((hr + 4) & 255) << 8;
    for (int i = 0; i < 32; i++) {
        int idx = (i << 8) + tid;
        int c = idx >> 5, wp = idx & 31;
        s[c][wp] = x[(size_t)((b << 8) + c)*65536 + hs + ((w0 + wp + 4) & 255)];
    }
    __syncthreads();
    size_t t = (size_t)(b << 16) + (hr << 8) + w0 + lane;
    int c0 = wid << 5;
    for (int j = 0; j < 32; j += 8) {
        __nv_bfloat16 hv[8], lv[8];
#pragma unroll
        for (int e = 0; e < 8; e++) {
            float a = s[c0 + j + e][lane];
            hv[e] = __float2bfloat16(a);
            lv[e] = __float2bfloat16(a - bf2f(hv[e]));
        }
        *(uint4*)&g_xh[t*256 + c0 + j] = *(uint4*)hv;
        *(uint4*)&g_xl[t*256 + c0 + j] = *(uint4*)lv;
    }
}

// ---------------- epilogues ----------------
struct EQKVt {
    const float* bias;
    __device__ void st2(int m, int n, int z, float v0, float v1) const {
        v0 += bias[n]; v1 += bias[n+1];
        if (n < 256) {
            *(float2*)&g_q[(size_t)m*256 + n] = make_float2(v0, v1);
        } else if (n < 512) {
            int c = n - 256;
            __nv_bfloat16 h0 = __float2bfloat16(v0), h1 = __float2bfloat16(v1);
            *(__nv_bfloat162*)&g_kh[(size_t)m*256 + c] = __halves2bfloat162(h0, h1);
            *(__nv_bfloat162*)&g_kl[(size_t)m*256 + c] = __halves2bfloat162(
                __float2bfloat16(v0 - bf2f(h0)), __float2bfloat16(v1 - bf2f(h1)));
        } else {
            int c = n - 512;
            __nv_bfloat16 h0 = __float2bfloat16(v0), h1 = __float2bfloat16(v1);
            *(__nv_bfloat162*)&g_vh[(size_t)m*256 + c] = __halves2bfloat162(h0, h1);
            *(__nv_bfloat162*)&g_vl[(size_t)m*256 + c] = __halves2bfloat162(
                __float2bfloat16(v0 - bf2f(h0)), __float2bfloat16(v1 - bf2f(h1)));
        }
    }
};
struct ESQ {
    static constexpr bool HAS_POOL = true;
    __device__ void st2(int m, int n, int z, float v0, float v1) const {
        __nv_bfloat16 h0 = __float2bfloat16(v0), h1 = __float2bfloat16(v1);
        __nv_bfloat16 l0 = __float2bfloat16(v0 - bf2f(h0)), l1 = __float2bfloat16(v1 - bf2f(h1));
        if (n < 64) {
            *(__nv_bfloat162*)&g_uphi[(size_t)m*64 + n] = __halves2bfloat162(h0, h1);
            *(__nv_bfloat162*)&g_uplo[(size_t)m*64 + n] = __halves2bfloat162(l0, l1);
        } else {
            int nl = n - 64;
            *(__nv_bfloat162*)&g_ulsh[(size_t)m*64 + nl] = __halves2bfloat162(h0, h1);
            *(__nv_bfloat162*)&g_ulsl[(size_t)m*64 + nl] = __halves2bfloat162(l0, l1);
        }
    }
    __device__ int pslot(int n, int b) const { return n >= 64 ? (b << 9) + 448 + (n - 64) : -1; }
};
struct EY2h {
    static constexpr bool HAS_POOL = true;
    __device__ void st2(int m, int n, int z, float v0, float v1) const {
        if (n < 192) *(float2*)&g_y2[(size_t)m*192 + n] = make_float2(v0, v1);
    }
    __device__ int pslot(int n, int b) const { return n < 192 ? (b << 9) + 256 + n : -1; }
};

// ---------------- WIDE dedup split HMMA GEMM: 128M x 256N tile ----------------
// stage (72KB): [Ah | Al | B1h | B2h | B1l | B2l], each 6144 elems (2 groups x 128 x 24)
template<bool GN, class EF>
__global__ __launch_bounds__(256, 1) void hgemmW(const __nv_bfloat16* __restrict__ Ah_,
                                                 const __nv_bfloat16* __restrict__ Al_,
                                                 const __nv_bfloat16* __restrict__ Bh_,
                                                 const __nv_bfloat16* __restrict__ Bl_,
                                                 int nk, EF ef) {
    extern __shared__ __nv_bfloat16 sm[];
    int tid = threadIdx.x, lane = tid & 31, wid = tid >> 5;
    int m0 = blockIdx.y << 7, n0 = blockIdx.x << 8;
    uint32_t sbase = smem_u32(sm);
    int wm = (wid & 3) << 5, wn2 = wid >> 2;      // warp: 32M x 128N; wn2 picks B half
    int gid = lane >> 2, tig = lane & 3;
    int lr = lane & 7, lh = (lane >> 3) & 1, lk = lane >> 4;
    uint32_t offA[2];
#pragma unroll
    for (int mf = 0; mf < 2; mf++)
        offA[mf] = (uint32_t)(((wm + (mf << 4) + lr + lh*8)*24 + lk*8) << 1);
    int lq = lane >> 3;
    uint32_t offB[8];
#pragma unroll
    for (int p = 0; p < 8; p++)
        offB[p] = (uint32_t)((((p << 4) + lr + (lq >> 1)*8)*24 + (lq & 1)*8) << 1);

    float acc[2][16][4];
#pragma unroll
    for (int mf = 0; mf < 2; mf++)
#pragma unroll
        for (int nf = 0; nf < 16; nf++)
#pragma unroll
            for (int e = 0; e < 4; e++) acc[mf][nf][e] = 0.f;

    auto prefetch = [&](int ch, int s) {
        int k0 = ch << 5;
#pragma unroll
        for (int i = 0; i < 12; i++) {
            int tvec = (i << 8) + tid;          // 0..3071
            int st = tvec >> 9;                 // 0..5
            int w = tvec & 511;
            int r = w >> 2, c4 = w & 3;
            uint32_t da = sbase + (uint32_t)(s*73728 + st*12288
                          + ((((c4 >> 1)*128 + r)*24 + (c4 & 1)*8) << 1));
            const __nv_bfloat16* src;
            if (st < 2) {
                src = (st ? Al_ : Ah_) + (size_t)(m0 + r)*256 + k0 + (c4 << 3);
            } else {
                int sub = st - 2;
                const __nv_bfloat16* bp = (sub < 2) ? Bh_ : Bl_;
                src = bp + (size_t)(n0 + ((sub & 1) << 7) + r)*256 + k0 + (c4 << 3);
            }
            CP_A16(da, src);
        }
        CP_COMMIT();
    };
    prefetch(0, 0);
    for (int ch = 0; ch < nk; ch++) {
        if (ch + 1 < nk) prefetch(ch + 1, (ch + 1) & 1);
        else CP_COMMIT();
        CP_WAIT1();
        __syncthreads();
        uint32_t stb = sbase + (uint32_t)((ch & 1)*73728);
        uint32_t ahb = stb, alb = stb + 12288;
        uint32_t bhb = stb + (uint32_t)((2 + wn2)*12288);
        uint32_t blb = stb + (uint32_t)((4 + wn2)*12288);
#pragma unroll
        for (int g = 0; g < 2; g++) {
            uint32_t go = (uint32_t)(g*6144);
#pragma unroll
            for (int half = 0; half < 2; half++) {
                float (*ac)[4] = nullptr;
                uint32_t a[2][4], b[8][2];
                int pb = half << 2;
                ldsm4(b[0][0], b[0][1], b[1][0], b[1][1], bhb + go + offB[pb]);
                ldsm4(b[2][0], b[2][1], b[3][0], b[3][1], bhb + go + offB[pb+1]);
                ldsm4(b[4][0], b[4][1], b[5][0], b[5][1], bhb + go + offB[pb+2]);
                ldsm4(b[6][0], b[6][1], b[7][0], b[7][1], bhb + go + offB[pb+3]);
                ldsm4(a[0][0], a[0][1], a[0][2], a[0][3], ahb + go + offA[0]);
                ldsm4(a[1][0], a[1][1], a[1][2], a[1][3], ahb + go + offA[1]);
#pragma unroll
                for (int mf = 0; mf < 2; mf++)
#pragma unroll
                    for (int nf = 0; nf < 8; nf++)
                        mma16816(acc[mf][(half << 3) + nf], a[mf], b[nf]);
                ldsm4(a[0][0], a[0][1], a[0][2], a[0][3], alb + go + offA[0]);
                ldsm4(a[1][0], a[1][1], a[1][2], a[1][3], alb + go + offA[1]);
#pragma unroll
                for (int mf = 0; mf < 2; mf++)
#pragma unroll
                    for (int nf = 0; nf < 8; nf++)
                        mma16816(acc[mf][(half << 3) + nf], a[mf], b[nf]);
                ldsm4(b[0][0], b[0][1], b[1][0], b[1][1], blb + go + offB[pb]);
                ldsm4(b[2][0], b[2][1], b[3][0], b[3][1], blb + go + offB[pb+1]);
                ldsm4(b[4][0], b[4][1], b[5][0], b[5][1], blb + go + offB[pb+2]);
                ldsm4(b[6][0], b[6][1], b[7][0], b[7][1], blb + go + offB[pb+3]);
                ldsm4(a[0][0], a[0][1], a[0][2], a[0][3], ahb + go + offA[0]);
                ldsm4(a[1][0], a[1][1], a[1][2], a[1][3], ahb + go + offA[1]);
#pragma unroll
                for (int mf = 0; mf < 2; mf++)
#pragma unroll
                    for (int nf = 0; nf < 8; nf++)
                        mma16816(acc[mf][(half << 3) + nf], a[mf], b[nf]);
                (void)ac;
            }
        }
        __syncthreads();
    }
#pragma unroll
    for (int mf = 0; mf < 2; mf++) {
        int row0 = m0 + wm + (mf << 4) + gid;
#pragma unroll
        for (int nf = 0; nf < 16; nf++) {
            int col = n0 + (wn2 << 7) + (nf << 3) + (tig << 1);
            ef.st2(row0,     col, 0, acc[mf][nf][0], acc[mf][nf][1]);
            ef.st2(row0 + 8, col, 0, acc[mf][nf][2], acc[mf][nf][3]);
        }
    }
    if constexpr (GN) {
        if (blockIdx.x == 0) {      // n0==0: exactly the q columns
            float* redS = (float*)sm;
            float* redQ = redS + 8192;
            int contrib = ((wid & 3) << 3) + gid;
#pragma unroll
            for (int nf = 0; nf < 16; nf++)
#pragma unroll
                for (int j = 0; j < 2; j++) {
                    int col = (wn2 << 7) + (nf << 3) + (tig << 1) + j;
                    float bb = ef.bias[col];
                    float v0 = acc[0][nf][j]   + bb, v1 = acc[0][nf][j+2] + bb;
                    float v2 = acc[1][nf][j]   + bb, v3 = acc[1][nf][j+2] + bb;
                    redS[col*32 + contrib] = v0 + v1 + v2 + v3;
                    redQ[col*32 + contrib] = v0*v0 + v1*v1 + v2*v2 + v3*v3;
                }
            __syncthreads();
            float s = 0.f, s2 = 0.f;
#pragma unroll
            for (int c2 = 0; c2 < 32; c2++) { s += redS[tid*32 + c2]; s2 += redQ[tid*32 + c2]; }
            int g = tid >> 4, bb = m0 >> 16;
            atomicAdd(&g_gnstats[((bb << 4) + g)*2],     s);
            atomicAdd(&g_gnstats[((bb << 4) + g)*2 + 1], s2);
        }
    }
}

// ---------------- WIDE out-projection with fused NCHW roll-scatter ----------------
__global__ __launch_bounds__(256, 1) void hgemmOW(const __nv_bfloat16* __restrict__ Ah_,
                                                  const __nv_bfloat16* __restrict__ Al_,
                                                  const __nv_bfloat16* __restrict__ Bh_,
                                                  const __nv_bfloat16* __restrict__ Bl_,
                                                  const float* __restrict__ bias,
                                                  float* __restrict__ out) {
    extern __shared__ __nv_bfloat16 sm[];
    int tid = threadIdx.x, lane = tid & 31, wid = tid >> 5;
    int m0 = blockIdx.y << 7;
    uint32_t sbase = smem_u32(sm);
    int wm = (wid & 3) << 5, wn2 = wid >> 2;
    int gid = lane >> 2, tig = lane & 3;
    int lr = lane & 7, lh = (lane >> 3) & 1, lk = lane >> 4;
    uint32_t offA[2];
#pragma unroll
    for (int mf = 0; mf < 2; mf++)
        offA[mf] = (uint32_t)(((wm + (mf << 4) + lr + lh*8)*24 + lk*8) << 1);
    int lq = lane >> 3;
    uint32_t offB[8];
#pragma unroll
    for (int p = 0; p < 8; p++)
        offB[p] = (uint32_t)((((p << 4) + lr + (lq >> 1)*8)*24 + (lq & 1)*8) << 1);

    float acc[2][16][4];
#pragma unroll
    for (int mf = 0; mf < 2; mf++)
#pragma unroll
        for (int nf = 0; nf < 16; nf++)
#pragma unroll
            for (int e = 0; e < 4; e++) acc[mf][nf][e] = 0.f;

    auto prefetch = [&](int ch, int s) {
        int k0 = ch << 5;
#pragma unroll
        for (int i = 0; i < 12; i++) {
            int tvec = (i << 8) + tid;
            int st = tvec >> 9;
            int w = tvec & 511;
            int r = w >> 2, c4 = w & 3;
            uint32_t da = sbase + (uint32_t)(s*73728 + st*12288
                          + ((((c4 >> 1)*128 + r)*24 + (c4 & 1)*8) << 1));
            const __nv_bfloat16* src;
            if (st < 2) {
                src = (st ? Al_ : Ah_) + (size_t)(m0 + r)*256 + k0 + (c4 << 3);
            } else {
                int sub = st - 2;
                const __nv_bfloat16* bp = (sub < 2) ? Bh_ : Bl_;
                src = bp + (size_t)((((sub & 1) << 7) + r))*256 + k0 + (c4 << 3);
            }
            CP_A16(da, src);
        }
        CP_COMMIT();
    };
    prefetch(0, 0);
    for (int ch = 0; ch < 8; ch++) {
        if (ch + 1 < 8) prefetch(ch + 1, (ch + 1) & 1);
        else CP_COMMIT();
        CP_WAIT1();
        __syncthreads();
        uint32_t stb = sbase + (uint32_t)((ch & 1)*73728);
        uint32_t ahb = stb, alb = stb + 12288;
        uint32_t bhb = stb + (uint32_t)((2 + wn2)*12288);
        uint32_t blb = stb + (uint32_t)((4 + wn2)*12288);
#pragma unroll
        for (int g = 0; g < 2; g++) {
            uint32_t go = (uint32_t)(g*6144);
#pragma unroll
            for (int half = 0; half < 2; half++) {
                uint32_t a[2][4], b[8][2];
                int pb = half << 2;
                ldsm4(b[0][0], b[0][1], b[1][0], b[1][1], bhb + go + offB[pb]);
                ldsm4(b[2][0], b[2][1], b[3][0], b[3][1], bhb + go + offB[pb+1]);
                ldsm4(b[4][0], b[4][1], b[5][0], b[5][1], bhb + go + offB[pb+2]);
                ldsm4(b[6][0], b[6][1], b[7][0], b[7][1], bhb + go + offB[pb+3]);
                ldsm4(a[0][0], a[0][1], a[0][2], a[0][3], ahb + go + offA[0]);
                ldsm4(a[1][0], a[1][1], a[1][2], a[1][3], ahb + go + offA[1]);
#pragma unroll
                for (int mf = 0; mf < 2; mf++)
#pragma unroll
                    for (int nf = 0; nf < 8; nf++)
                        mma16816(acc[mf][(half << 3) + nf], a[mf], b[nf]);
                ldsm4(a[0][0], a[0][1], a[0][2], a[0][3], alb + go + offA[0]);
                ldsm4(a[1][0], a[1][1], a[1][2], a[1][3], alb + go + offA[1]);
#pragma unroll
                for (int mf = 0; mf < 2; mf++)
#pragma unroll
                    for (int nf = 0; nf < 8; nf++)
                        mma16816(acc[mf][(half << 3) + nf], a[mf], b[nf]);
                ldsm4(b[0][0], b[0][1], b[1][0], b[1][1], blb + go + offB[pb]);
                ldsm4(b[2][0], b[2][1], b[3][0], b[3][1], blb + go + offB[pb+1]);
                ldsm4(b[4][0], b[4][1], b[5][0], b[5][1], blb + go + offB[pb+2]);
                ldsm4(b[6][0], b[6][1], b[7][0], b[7][1], blb + go + offB[pb+3]);
                ldsm4(a[0][0], a[0][1], a[0][2], a[0][3], ahb + go + offA[0]);
                ldsm4(a[1][0], a[1][1], a[1][2], a[1][3], ahb + go + offA[1]);
#pragma unroll
                for (int mf = 0; mf < 2; mf++)
#pragma unroll
                    for (int nf = 0; nf < 8; nf++)
                        mma16816(acc[mf][(half << 3) + nf], a[mf], b[nf]);
            }
        }
        __syncthreads();
    }
    // staged NCHW roll-scatter: 4 chunks of 32 rows x 256 cols
    const int SP = 260;
    float* stage = (float*)sm;
#pragma unroll
    for (int chunk = 0; chunk < 4; chunk++) {
#pragma unroll
        for (int mf = 0; mf < 2; mf++) {
            int r0 = wm + (mf << 4) + gid;
#pragma unroll
            for (int rr = 0; rr < 2; rr++) {
                int r = r0 + (rr << 3);
                if ((r >> 5) == chunk) {
                    int rl = r & 31;
#pragma unroll
                    for (int nf = 0; nf < 16; nf++) {
                        int cl = (wn2 << 7) + (nf << 3) + (tig << 1);
                        stage[rl*SP + cl]     = acc[mf][nf][rr*2]     + bias[cl];
                        stage[rl*SP + cl + 1] = acc[mf][nf][rr*2 + 1] + bias[cl + 1];
                    }
                }
            }
        }
        __syncthreads();
        int m = m0 + (chunk << 5) + lane;
        int b = m >> 16, pixi = m & 65535;
        int hr = pixi >> 8, wr = pixi & 255;
        size_t pbase = (size_t)(((hr + 4) & 255) << 8) + ((wr + 4) & 255);
        for (int nl = wid; nl < 256; nl += 8)
            out[(size_t)((b << 8) + nl)*65536 + pbase] = stage[lane*SP + nl];
        __syncthreads();
    }
}

// ---------------- dedup split HMMA GEMM (small: sq / pwc2) ----------------
template<class EF>
__global__ __launch_bounds__(256, 2) void hgemmA(const __nv_bfloat16* __restrict__ Ah_,
                                                 const __nv_bfloat16* __restrict__ Al_, int lda,
                                                 const __nv_bfloat16* __restrict__ Bh_,
                                                 const __nv_bfloat16* __restrict__ Bl_, int ldb,
                                                 int nk, EF ef) {
    extern __shared__ __nv_bfloat16 sm[];
    int tid = threadIdx.x, lane = tid & 31, wid = tid >> 5;
    int m0 = blockIdx.y << 7, n0 = blockIdx.x << 7;
    uint32_t sbase = smem_u32(sm);
    int wm = (wid & 3) << 5, wn = (wid >> 2) << 6;
    int gid = lane >> 2, tig = lane & 3;
    int lr = lane & 7, lh = (lane >> 3) & 1, lk = lane >> 4;
    uint32_t offA[2];
#pragma unroll
    for (int mf = 0; mf < 2; mf++)
        offA[mf] = (uint32_t)(((wm + (mf << 4) + lr + lh*8)*24 + lk*8) << 1);
    int lq = lane >> 3;
    uint32_t offB[4];
#pragma unroll
    for (int p = 0; p < 4; p++)
        offB[p] = (uint32_t)(((wn + (p << 4) + lr + (lq >> 1)*8)*24 + (lq & 1)*8) << 1);

    float acc[2][8][4];
#pragma unroll
    for (int mf = 0; mf < 2; mf++)
#pragma unroll
        for (int nf = 0; nf < 8; nf++)
#pragma unroll
            for (int e = 0; e < 4; e++) acc[mf][nf][e] = 0.f;

    auto prefetch = [&](int ch, int s) {
        int k0 = ch << 5;
#pragma unroll
        for (int i = 0; i < 2; i++) {
            int idx = (i << 8) + tid;
            int r = idx >> 2, c4 = idx & 3;
            int g = c4 >> 1, ke = c4 & 1;
            uint32_t da = sbase + (uint32_t)((s*24576 + (g*128 + r)*24 + ke*8) << 1);
            size_t asrc = (size_t)(m0 + r)*lda + k0 + (c4 << 3);
            size_t bsrc = (size_t)(n0 + r)*ldb + k0 + (c4 << 3);
            CP_A16(da,          Ah_ + asrc);
            CP_A16(da + 12288,  Al_ + asrc);
            CP_A16(da + 24576,  Bh_ + bsrc);
            CP_A16(da + 36864,  Bl_ + bsrc);
        }
        CP_COMMIT();
    };
    prefetch(0, 0);
    for (int ch = 0; ch < nk; ch++) {
        if (ch + 1 < nk) prefetch(ch + 1, (ch + 1) & 1);
        else CP_COMMIT();
        CP_WAIT1();
        __syncthreads();
        uint32_t stb = sbase + (uint32_t)((ch & 1)*49152);
#pragma unroll
        for (int g = 0; g < 2; g++) {
            uint32_t gb = stb + (uint32_t)(g*6144);
            uint32_t a[2][4], b[8][2];
            ldsm4(b[0][0], b[0][1], b[1][0], b[1][1], gb + 24576 + offB[0]);
            ldsm4(b[2][0], b[2][1], b[3][0], b[3][1], gb + 24576 + offB[1]);
            ldsm4(b[4][0], b[4][1], b[5][0], b[5][1], gb + 24576 + offB[2]);
            ldsm4(b[6][0], b[6][1], b[7][0], b[7][1], gb + 24576 + offB[3]);
            ldsm4(a[0][0], a[0][1], a[0][2], a[0][3], gb + offA[0]);
            ldsm4(a[1][0], a[1][1], a[1][2], a[1][3], gb + offA[1]);
#pragma unroll
            for (int mf = 0; mf < 2; mf++)
#pragma unroll
                for (int nf = 0; nf < 8; nf++)
                    mma16816(acc[mf][nf], a[mf], b[nf]);
            ldsm4(a[0][0], a[0][1], a[0][2], a[0][3], gb + 12288 + offA[0]);
            ldsm4(a[1][0], a[1][1], a[1][2], a[1][3], gb + 12288 + offA[1]);
#pragma unroll
            for (int mf = 0; mf < 2; mf++)
#pragma unroll
                for (int nf = 0; nf < 8; nf++)
                    mma16816(acc[mf][nf], a[mf], b[nf]);
            ldsm4(b[0][0], b[0][1], b[1][0], b[1][1], gb + 36864 + offB[0]);
            ldsm4(b[2][0], b[2][1], b[3][0], b[3][1], gb + 36864 + offB[1]);
            ldsm4(b[4][0], b[4][1], b[5][0], b[5][1], gb + 36864 + offB[2]);
            ldsm4(b[6][0], b[6][1], b[7][0], b[7][1], gb + 36864 + offB[3]);
            ldsm4(a[0][0], a[0][1], a[0][2], a[0][3], gb + offA[0]);
            ldsm4(a[1][0], a[1][1], a[1][2], a[1][3], gb + offA[1]);
#pragma unroll
            for (int mf = 0; mf < 2; mf++)
#pragma unroll
                for (int nf = 0; nf < 8; nf++)
                    mma16816(acc[mf][nf], a[mf], b[nf]);
        }
        __syncthreads();
    }
#pragma unroll
    for (int mf = 0; mf < 2; mf++) {
        int row0 = m0 + wm + (mf << 4) + gid;
#pragma unroll
        for (int nf = 0; nf < 8; nf++) {
            int col = n0 + wn + (nf << 3) + (tig << 1);
            ef.st2(row0,     col, 0, acc[mf][nf][0], acc[mf][nf][1]);
            ef.st2(row0 + 8, col, 0, acc[mf][nf][2], acc[mf][nf][3]);
        }
    }
    if constexpr (EF::HAS_POOL) {
        float* red = (float*)sm;
        int contrib = ((wid & 3) << 3) + gid;
#pragma unroll
        for (int nf = 0; nf < 8; nf++)
#pragma unroll
            for (int j = 0; j < 2; j++) {
                float p = acc[0][nf][j] + acc[0][nf][j+2] + acc[1][nf][j] + acc[1][nf][j+2];
                red[(wn + (nf << 3) + (tig << 1) + j)*32 + contrib] = p;
            }
        __syncthreads();
        if (tid < 128) {
            float s = 0.f;
#pragma unroll
            for (int c2 = 0; c2 < 32; c2++) s += red[tid*32 + c2];
            int slot = ef.pslot(n0 + tid, m0 >> 16);
            if (slot >= 0) atomicAdd(&g_pool[slot], s);
        }
    }
}

// ---------------- conv GEMM: dedup split + async gather prefetch + fused pool ----------------
__global__ __launch_bounds__(256, 2) void hgemmC(const __nv_bfloat16* __restrict__ Bh_,
                                                 const __nv_bfloat16* __restrict__ Bl_,
                                                 const float* __restrict__ bias) {
    extern __shared__ __nv_bfloat16 sm[];
    int tid = threadIdx.x, lane = tid & 31, wid = tid >> 5;
    int m0 = blockIdx.y << 7, z = blockIdx.z;
    uint32_t sbase = smem_u32(sm);
    int wm = (wid & 3) << 5, wn = (wid >> 2) << 6;
    int gid = lane >> 2, tig = lane & 3;
    int lr = lane & 7, lh = (lane >> 3) & 1, lk = lane >> 4;
    uint32_t offA[2];
#pragma unroll
    for (int mf = 0; mf < 2; mf++)
        offA[mf] = (uint32_t)(((wm + (mf << 4) + lr + lh*8)*24 + lk*8) << 1);
    int lq = lane >> 3;
    uint32_t offB[4];
#pragma unroll
    for (int p = 0; p < 4; p++)
        offB[p] = (uint32_t)(((wn + (p << 4) + lr + (lq >> 1)*8)*24 + (lq & 1)*8) << 1);

    float acc[2][8][4];
#pragma unroll
    for (int mf = 0; mf < 2; mf++)
#pragma unroll
        for (int nf = 0; nf < 8; nf++)
#pragma unroll
            for (int e = 0; e < 4; e++) acc[mf][nf][e] = 0.f;

    const __nv_bfloat16* Bzh = Bh_ + (size_t)z*128*352;
    const __nv_bfloat16* Bzl = Bl_ + (size_t)z*128*352;

    auto prefetch = [&](int ch, int s) {
        int k0 = ch << 5;
#pragma unroll
        for (int i = 0; i < 2; i++) {
            int idx = (i << 8) + tid;
            int r = idx >> 2, c4 = idx & 3;
            int g = c4 >> 1, ke = c4 & 1;
            uint32_t da = sbase + (uint32_t)((s*24576 + (g*128 + r)*24 + ke*8) << 1);
            int k = k0 + (c4 << 3);
            int m = m0 + r;
            size_t aoff; int sz = 16;
            if (k < 288) {
                int tap = k >> 5, kl0 = k & 31;
                int dy = tap/3 - 1, dx = tap - (tap/3)*3 - 1;
                int b = m >> 16;
                int hr = ((m >> 8) & 255) + dy, wr = (m & 255) + dx;
                if ((unsigned)hr > 255u || (unsigned)wr > 255u) sz = 0;
                aoff = (size_t)((b << 16) + ((hr & 255) << 8) + (wr & 255))*64 + (z << 5) + kl0;
            } else {
                aoff = (size_t)m*64 + (k - 288);
            }
            CP_A16Z(da,         g_uphi + aoff, sz);
            CP_A16Z(da + 12288, g_uplo + aoff, sz);
            size_t boff = (size_t)r*352 + k;
            CP_A16(da + 24576, Bzh + boff);
            CP_A16(da + 36864, Bzl + boff);
        }
        CP_COMMIT();
    };
    prefetch(0, 0);
    for (int ch = 0; ch < 11; ch++) {
        if (ch + 1 < 11) prefetch(ch + 1, (ch + 1) & 1);
        else CP_COMMIT();
        CP_WAIT1();
        __syncthreads();
        uint32_t stb = sbase + (uint32_t)((ch & 1)*49152);
#pragma unroll
        for (int g = 0; g < 2; g++) {
            uint32_t gb = stb + (uint32_t)(g*6144);
            uint32_t a[2][4], b[8][2];
            ldsm4(b[0][0], b[0][1], b[1][0], b[1][1], gb + 24576 + offB[0]);
            ldsm4(b[2][0], b[2][1], b[3][0], b[3][1], gb + 24576 + offB[1]);
            ldsm4(b[4][0], b[4][1], b[5][0], b[5][1], gb + 24576 + offB[2]);
            ldsm4(b[6][0], b[6][1], b[7][0], b[7][1], gb + 24576 + offB[3]);
            ldsm4(a[0][0], a[0][1], a[0][2], a[0][3], gb + offA[0]);
            ldsm4(a[1][0], a[1][1], a[1][2], a[1][3], gb + offA[1]);
#pragma unroll
            for (int mf = 0; mf < 2; mf++)
#pragma unroll
                for (int nf = 0; nf < 8; nf++)
                    mma16816(acc[mf][nf], a[mf], b[nf]);
            ldsm4(a[0][0], a[0][1], a[0][2], a[0][3], gb + 12288 + offA[0]);
            ldsm4(a[1][0], a[1][1], a[1][2], a[1][3], gb + 12288 + offA[1]);
#pragma unroll
            for (int mf = 0; mf < 2; mf++)
#pragma unroll
                for (int nf = 0; nf < 8; nf++)
                    mma16816(acc[mf][nf], a[mf], b[nf]);
            ldsm4(b[0][0], b[0][1], b[1][0], b[1][1], gb + 36864 + offB[0]);
            ldsm4(b[2][0], b[2][1], b[3][0], b[3][1], gb + 36864 + offB[1]);
            ldsm4(b[4][0], b[4][1], b[5][0], b[5][1], gb + 36864 + offB[2]);
            ldsm4(b[6][0], b[6][1], b[7][0], b[7][1], gb + 36864 + offB[3]);
            ldsm4(a[0][0], a[0][1], a[0][2], a[0][3], gb + offA[0]);
            ldsm4(a[1][0], a[1][1], a[1][2], a[1][3], gb + offA[1]);
#pragma unroll
            for (int mf = 0; mf < 2; mf++)
#pragma unroll
                for (int nf = 0; nf < 8; nf++)
                    mma16816(acc[mf][nf], a[mf], b[nf]);
        }
        __syncthreads();
    }
#pragma unroll
    for (int mf = 0; mf < 2; mf++) {
        int row0 = m0 + wm + (mf << 4) + gid;
#pragma unroll
        for (int nf = 0; nf < 8; nf++) {
            int col = wn + (nf << 3) + (tig << 1);
            int c = (z << 7) + col;
            *(float2*)&g_y1[(size_t)row0*256 + c] =
                make_float2(acc[mf][nf][0] + bias[c], acc[mf][nf][1] + bias[c+1]);
            *(float2*)&g_y1[(size_t)(row0 + 8)*256 + c] =
                make_float2(acc[mf][nf][2] + bias[c], acc[mf][nf][3] + bias[c+1]);
        }
    }
    {
        float* red = (float*)sm;
        int contrib = ((wid & 3) << 3) + gid;
#pragma unroll
        for (int nf = 0; nf < 8; nf++)
#pragma unroll
            for (int j = 0; j < 2; j++) {
                int col = wn + (nf << 3) + (tig << 1) + j;
                float bb = bias[(z << 7) + col];
                float p = acc[0][nf][j] + acc[0][nf][j+2] + acc[1][nf][j] + acc[1][nf][j+2] + 4.f*bb;
                red[col*32 + contrib] = p;
            }
        __syncthreads();
        if (tid < 128) {
            float s = 0.f;
#pragma unroll
            for (int c2 = 0; c2 < 32; c2++) s += red[tid*32 + c2];
            atomicAdd(&g_pool[((m0 >> 16) << 9) + (z << 7) + tid], s);
        }
    }
}

// ---------------- SRU / softmax ----------------
__global__ void sru_elem(const float* __restrict__ gn_w, const float* __restrict__ gn_b) {
    int i = blockIdx.x*256 + threadIdx.x;
    int t = i >> 7, cp = i & 127;
    int b = t >> 16;
    int c1 = cp, c2 = cp + 128;
    float wsum = g_misc[0];
    int g1 = c1 >> 4, g2 = c2 >> 4;
    float m1 = g_gnstats[((b<<4)+g1)*2] / GN_N;
    float v1 = g_gnstats[((b<<4)+g1)*2+1] / GN_N - m1*m1;
    float m2 = g_gnstats[((b<<4)+g2)*2] / GN_N;
    float v2 = g_gnstats[((b<<4)+g2)*2+1] / GN_N - m2*m2;
    float w1c = gn_w[c1], w2c = gn_w[c2];
    float A1 = rsqrtf(v1 + 1e-5f)*w1c, B1 = gn_b[c1] - m1*rsqrtf(v1 + 1e-5f)*w1c;
    float A2 = rsqrtf(v2 + 1e-5f)*w2c, B2 = gn_b[c2] - m2*rsqrtf(v2 + 1e-5f)*w2c;
    float x1 = g_q[(size_t)t*256 + c1], x2 = g_q[(size_t)t*256 + c2];
    float rw1 = 1.0f/(1.0f + expf(-(x1*A1 + B1)*(w1c/wsum)));
    float rw2 = 1.0f/(1.0f + expf(-(x2*A2 + B2)*(w2c/wsum)));
    float w11 = rw1 > 0.5f ? 1.0f : rw1, w21 = rw1 > 0.5f ? 0.0f : rw1;
    float w12 = rw2 > 0.5f ? 1.0f : rw2, w22 = rw2 > 0.5f ? 0.0f : rw2;
    float o1 = w11*x1 + w22*x2;
    float o2 = w12*x2 + w21*x1;
    __nv_bfloat16 h1 = __float2bfloat16(o1), h2 = __float2bfloat16(o2);
    g_qah[(size_t)t*256 + c1] = h1;
    g_qal[(size_t)t*256 + c1] = __float2bfloat16(o1 - bf2f(h1));
    g_qah[(size_t)t*256 + c2] = h2;
    g_qal[(size_t)t*256 + c2] = __float2bfloat16(o2 - bf2f(h2));
}
__global__ void softmax512() {
    int b = blockIdx.x, t = threadIdx.x;
    __shared__ float sh[512];
    float v = g_pool[(b << 9) + t] * (1.0f/65536.0f);
    sh[t] = v;
    __syncthreads();
    for (int st = 256; st > 0; st >>= 1) { if (t < st) sh[t] = fmaxf(sh[t], sh[t + st]); __syncthreads(); }
    float mx = sh[0];
    __syncthreads();
    float e = expf(v - mx);
    sh[t] = e;
    __syncthreads();
    for (int st = 256; st > 0; st >>= 1) { if (t < st) sh[t] += sh[t + st]; __syncthreads(); }
    float sum = sh[0];
    __syncthreads();
    g_pool[(b << 9) + t] = e / sum;
}

// ---------------- HMMA windowed attention (fused CRU combine in K staging) ----------------
__global__ __launch_bounds__(128) void attn_mma(const float* __restrict__ rel_pos) {
    extern __shared__ __nv_bfloat16 smb[];
    float* rps = (float*)(smb + 49152);
    int tid = threadIdx.x, lane = tid & 31, wid = tid >> 5;
    int win = blockIdx.x, hg = blockIdx.y, b = blockIdx.z;
    int wy = win >> 5, wx = win & 31;
    int t0 = (b << 16) + (wy << 11) + (wx << 3);
    for (int i = 0; i < 8; i++) {
        int idx = (i << 7) + tid;
        int hh = idx >> 8, r = idx & 255;
        int tok = r >> 2, c8 = (r & 3) << 3;
        int token = t0 + ((tok >> 3) << 8) + (tok & 7);
        int cg = (((hg << 2) + hh) << 5) + c8;
        float4 ya = *(const float4*)&g_y1[(size_t)token*256 + cg];
        float4 yb = *(const float4*)&g_y1[(size_t)token*256 + cg + 4];
        float y1v[8] = {ya.x, ya.y, ya.z, ya.w, yb.x, yb.y, yb.z, yb.w};
        float y2v[8];
        if (cg < 192) {
            float4 za = *(const float4*)&g_y2[(size_t)token*192 + cg];
            float4 zb = *(const float4*)&g_y2[(size_t)token*192 + cg + 4];
            y2v[0]=za.x; y2v[1]=za.y; y2v[2]=za.z; y2v[3]=za.w;
            y2v[4]=zb.x; y2v[5]=zb.y; y2v[6]=zb.z; y2v[7]=zb.w;
        } else {
            int nl = cg - 192;
            uint4 uh = *(const uint4*)&g_ulsh[(size_t)token*64 + nl];
            uint4 ul = *(const uint4*)&g_ulsl[(size_t)token*64 + nl];
            const __nv_bfloat16* ph = (const __nv_bfloat16*)&uh;
            const __nv_bfloat16* pl = (const __nv_bfloat16*)&ul;
#pragma unroll
            for (int e = 0; e < 8; e++) y2v[e] = bf2f(ph[e]) + bf2f(pl[e]);
        }
        __nv_bfloat16 hv[8], lv[8];
#pragma unroll
        for (int e = 0; e < 8; e++) {
            float o = __ldg(&g_pool[(b << 9) + cg + e])*y1v[e]
                    + __ldg(&g_pool[(b << 9) + 256 + cg + e])*y2v[e];
            hv[e] = __float2bfloat16(o);
            lv[e] = __float2bfloat16(o - bf2f(hv[e]));
        }
        int dst = hh*12288 + ((c8 >> 4)*64 + tok)*24 + (c8 & 15);
        *(uint4*)&smb[dst]        = *(uint4*)hv;
        *(uint4*)&smb[dst + 3072] = *(uint4*)lv;
    }
    for (int i = 0; i < 32; i++) {
        int idx = (i << 7) + tid;
        int hh = idx >> 10, r = idx & 1023;
        int tok = r >> 4, dp = (r & 15) << 1;
        int token = t0 + ((tok >> 3) << 8) + (tok & 7);
        size_t src = (size_t)token*256 + (((hg << 2) + hh) << 5) + dp;
        __nv_bfloat162 vh = *(const __nv_bfloat162*)&g_vh[src];
        __nv_bfloat162 vl = *(const __nv_bfloat162*)&g_vl[src];
        int base = hh*12288 + 6144 + (tok >> 4)*768 + (tok & 15);
        smb[base + dp*24]            = vh.x;
        smb[base + (dp+1)*24]        = vh.y;
        smb[base + 3072 + dp*24]     = vl.x;
        smb[base + 3072 + (dp+1)*24] = vl.y;
    }
    for (int i = tid; i < 900; i += 128) {
        int hh = i / 225, r = i - hh*225;
        rps[i] = rel_pos[(((hg << 2) + hh))*225 + r];
    }
    __syncthreads();

    int hh = wid;
    uint32_t tb = smem_u32(smb) + (uint32_t)(hh*24576);
    uint32_t khb = tb, klb = tb + 6144, vhb = tb + 12288, vlb = tb + 18432;
    const float* rp = rps + hh*225;
    int gid = lane >> 2, tig = lane & 3;
    int lr = lane & 7, lq = lane >> 3;
    uint32_t offK[4], offV[2];
#pragma unroll
    for (int p = 0; p < 4; p++)
        offK[p] = (uint32_t)((((p << 4) + lr + (lq >> 1)*8)*24 + (lq & 1)*8) << 1);
#pragma unroll
    for (int p = 0; p < 2; p++)
        offV[p] = (uint32_t)((((p << 4) + lr + (lq >> 1)*8)*24 + (lq & 1)*8) << 1);
    bool lrm = wy == 31, lcm = wx == 31;
    int hbc = ((hg << 2) + hh) << 5;

    for (int half = 0; half < 2; half++) {
        int rbase = half << 5;
        uint32_t qh[2][2][4], ql[2][2][4];
#pragma unroll
        for (int mt = 0; mt < 2; mt++) {
            int r0 = rbase + (mt << 4) + gid;
            int tok0 = t0 + ((r0 >> 3) << 8) + (r0 & 7);
            int r1 = r0 + 8;
            int tok1 = t0 + ((r1 >> 3) << 8) + (r1 & 7);
#pragma unroll
            for (int kf = 0; kf < 2; kf++) {
                int kc = hbc + (kf << 4) + (tig << 1);
                qh[mt][kf][0] = *(const uint32_t*)&g_qah[(size_t)tok0*256 + kc];
                qh[mt][kf][1] = *(const uint32_t*)&g_qah[(size_t)tok1*256 + kc];
                qh[mt][kf][2] = *(const uint32_t*)&g_qah[(size_t)tok0*256 + kc + 8];
                qh[mt][kf][3] = *(const uint32_t*)&g_qah[(size_t)tok1*256 + kc + 8];
                ql[mt][kf][0] = *(const uint32_t*)&g_qal[(size_t)tok0*256 + kc];
                ql[mt][kf][1] = *(const uint32_t*)&g_qal[(size_t)tok1*256 + kc];
                ql[mt][kf][2] = *(const uint32_t*)&g_qal[(size_t)tok0*256 + kc + 8];
                ql[mt][kf][3] = *(const uint32_t*)&g_qal[(size_t)tok1*256 + kc + 8];
            }
        }
        float sacc[2][8][4];
#pragma unroll
        for (int mt = 0; mt < 2; mt++)
#pragma unroll
            for (int nt = 0; nt < 8; nt++)
#pragma unroll
                for (int e = 0; e < 4; e++) sacc[mt][nt][e] = 0.f;
#pragma unroll
        for (int kg = 0; kg < 2; kg++) {
            uint32_t bk[8][2];
            uint32_t kgb = khb + (uint32_t)(kg*3072);
            ldsm4(bk[0][0], bk[0][1], bk[1][0], bk[1][1], kgb + offK[0]);
            ldsm4(bk[2][0], bk[2][1], bk[3][0], bk[3][1], kgb + offK[1]);
            ldsm4(bk[4][0], bk[4][1], bk[5][0], bk[5][1], kgb + offK[2]);
            ldsm4(bk[6][0], bk[6][1], bk[7][0], bk[7][1], kgb + offK[3]);
#pragma unroll
            for (int mt = 0; mt < 2; mt++)
#pragma unroll
                for (int nt = 0; nt < 8; nt++) {
                    mma16816(sacc[mt][nt], qh[mt][kg], bk[nt]);
                    mma16816(sacc[mt][nt], ql[mt][kg], bk[nt]);
                }
            uint32_t lgb = klb + (uint32_t)(kg*3072);
            ldsm4(bk[0][0], bk[0][1], bk[1][0], bk[1][1], lgb + offK[0]);
            ldsm4(bk[2][0], bk[2][1], bk[3][0], bk[3][1], lgb + offK[1]);
            ldsm4(bk[4][0], bk[4][1], bk[5][0], bk[5][1], lgb + offK[2]);
            ldsm4(bk[6][0], bk[6][1], bk[7][0], bk[7][1], lgb + offK[3]);
#pragma unroll
            for (int mt = 0; mt < 2; mt++)
#pragma unroll
                for (int nt = 0; nt < 8; nt++)
                    mma16816(sacc[mt][nt], qh[mt][kg], bk[nt]);
        }
#pragma unroll
        for (int mt = 0; mt < 2; mt++)
#pragma unroll
            for (int rr = 0; rr < 2; rr++) {
                int row = rbase + (mt << 4) + gid + (rr << 3);
                int ph = row >> 3, pw = row & 7;
                float vv[16];
                float mx = -1e30f;
#pragma unroll
                for (int nt = 0; nt < 8; nt++)
#pragma unroll
                    for (int j = 0; j < 2; j++) {
                        int col = (nt << 3) + (tig << 1) + j;
                        int qy = col >> 3, qw = col & 7;
                        float v = sacc[mt][nt][rr*2 + j]*SCALE + rp[(ph - qy + 7)*15 + (pw - qw + 7)];
                        if ((lrm && ((ph < 4) != (qy < 4))) || (lcm && ((pw < 4) != (qw < 4)))) v = -1e30f;
                        vv[nt*2 + j] = v;
                        mx = fmaxf(mx, v);
                    }
                mx = fmaxf(mx, __shfl_xor_sync(0xffffffff, mx, 1));
                mx = fmaxf(mx, __shfl_xor_sync(0xffffffff, mx, 2));
                float s = 0.f;
#pragma unroll
                for (int e = 0; e < 16; e++) { vv[e] = expf(vv[e] - mx); s += vv[e]; }
                s += __shfl_xor_sync(0xffffffff, s, 1);
                s += __shfl_xor_sync(0xffffffff, s, 2);
                float inv = 1.0f / s;
#pragma unroll
                for (int nt = 0; nt < 8; nt++)
#pragma unroll
                    for (int j = 0; j < 2; j++)
                        sacc[mt][nt][rr*2 + j] = vv[nt*2 + j]*inv;
            }
        float oacc[2][4][4];
#pragma unroll
        for (int mt = 0; mt < 2; mt++)
#pragma unroll
            for (int nt = 0; nt < 4; nt++)
#pragma unroll
                for (int e = 0; e < 4; e++) oacc[mt][nt][e] = 0.f;
#pragma unroll
        for (int kf = 0; kf < 4; kf++) {
            uint32_t pfh[2][4], pfl[2][4];
#pragma unroll
            for (int mt = 0; mt < 2; mt++) {
#pragma unroll
                for (int e = 0; e < 4; e++) {
                    int nt = 2*kf + (e >> 1);
                    float p0 = sacc[mt][nt][(e & 1)*2];
                    float p1 = sacc[mt][nt][(e & 1)*2 + 1];
                    __nv_bfloat162 h2 = __floats2bfloat162_rn(p0, p1);
                    pfh[mt][e] = *(uint32_t*)&h2;
                    __nv_bfloat162 l2 = __floats2bfloat162_rn(p0 - bf2f(h2.x), p1 - bf2f(h2.y));
                    pfl[mt][e] = *(uint32_t*)&l2;
                }
            }
            uint32_t bv[4][2];
            uint32_t vgb = vhb + (uint32_t)(kf*1536);
            ldsm4(bv[0][0], bv[0][1], bv[1][0], bv[1][1], vgb + offV[0]);
            ldsm4(bv[2][0], bv[2][1], bv[3][0], bv[3][1], vgb + offV[1]);
#pragma unroll
            for (int mt = 0; mt < 2; mt++)
#pragma unroll
                for (int nt = 0; nt < 4; nt++) {
                    mma16816(oacc[mt][nt], pfh[mt], bv[nt]);
                    mma16816(oacc[mt][nt], pfl[mt], bv[nt]);
                }
            uint32_t lgb = vlb + (uint32_t)(kf*1536);
            ldsm4(bv[0][0], bv[0][1], bv[1][0], bv[1][1], lgb + offV[0]);
            ldsm4(bv[2][0], bv[2][1], bv[3][0], bv[3][1], lgb + offV[1]);
#pragma unroll
            for (int mt = 0; mt < 2; mt++)
#pragma unroll
                for (int nt = 0; nt < 4; nt++)
                    mma16816(oacc[mt][nt], pfh[mt], bv[nt]);
        }
#pragma unroll
        for (int mt = 0; mt < 2; mt++) {
            int r0 = rbase + (mt << 4) + gid;
            int tok0 = t0 + ((r0 >> 3) << 8) + (r0 & 7);
            int r1 = r0 + 8;
            int tok1 = t0 + ((r1 >> 3) << 8) + (r1 & 7);
#pragma unroll
            for (int nt = 0; nt < 4; nt++) {
                int c = hbc + (nt << 3) + (tig << 1);
                float a0 = oacc[mt][nt][0], a1 = oacc[mt][nt][1];
                float a2 = oacc[mt][nt][2], a3 = oacc[mt][nt][3];
                __nv_bfloat162 h0 = __floats2bfloat162_rn(a0, a1);
                __nv_bfloat162 h1 = __floats2bfloat162_rn(a2, a3);
                *(__nv_bfloat162*)&g_atth[(size_t)tok0*256 + c] = h0;
                *(__nv_bfloat162*)&g_atth[(size_t)tok1*256 + c] = h1;
                *(__nv_bfloat162*)&g_attl[(size_t)tok0*256 + c] =
                    __floats2bfloat162_rn(a0 - bf2f(h0.x), a1 - bf2f(h0.y));
                *(__nv_bfloat162*)&g_attl[(size_t)tok1*256 + c] =
                    __floats2bfloat162_rn(a2 - bf2f(h1.x), a3 - bf2f(h1.y));
            }
        }
    }
}

// ---------------- launch ----------------
extern "C" void kernel_launch(void* const* d_in, const int* in_sizes, int n_in,
                              void* d_out, int out_size) {
    const float* x      = (const float*)d_in[0];
    const float* w_qkv  = (const float*)d_in[1];
    const float* b_qkv  = (const float*)d_in[2];
    const float* rel_pos= (const float*)d_in[3];
    const float* gn_w   = (const float*)d_in[4];
    const float* gn_b   = (const float*)d_in[5];
    const float* sq1    = (const float*)d_in[6];
    const float* sq2    = (const float*)d_in[7];
    const float* gwc    = (const float*)d_in[8];
    const float* gwc_b  = (const float*)d_in[9];
    const float* pwc1   = (const float*)d_in[10];
    const float* pwc2   = (const float*)d_in[11];
    const float* w_out  = (const float*)d_in[12];
    const float* b_out  = (const float*)d_in[13];
    float* out = (float*)d_out;

    __nv_bfloat16 *p_bqh, *p_bql, *p_bouth, *p_boutl, *p_bsqh, *p_bsql, *p_bp2h, *p_bp2l;
    __nv_bfloat16 *p_xh, *p_xl, *p_kh, *p_kl, *p_atth, *p_attl, *p_ulsh, *p_ulsl;
    __nv_bfloat16 *p_bcvh, *p_bcvl;
    cudaGetSymbolAddress((void**)&p_bqh,   g_bqh);
    cudaGetSymbolAddress((void**)&p_bql,   g_bql);
    cudaGetSymbolAddress((void**)&p_bouth, g_bouth);
    cudaGetSymbolAddress((void**)&p_boutl, g_boutl);
    cudaGetSymbolAddress((void**)&p_bsqh,  g_bsqh);
    cudaGetSymbolAddress((void**)&p_bsql,  g_bsql);
    cudaGetSymbolAddress((void**)&p_bp2h,  g_bp2h);
    cudaGetSymbolAddress((void**)&p_bp2l,  g_bp2l);
    cudaGetSymbolAddress((void**)&p_xh,    g_xh);
    cudaGetSymbolAddress((void**)&p_xl,    g_xl);
    cudaGetSymbolAddress((void**)&p_kh,    g_kh);
    cudaGetSymbolAddress((void**)&p_kl,    g_kl);
    cudaGetSymbolAddress((void**)&p_atth,  g_atth);
    cudaGetSymbolAddress((void**)&p_attl,  g_attl);
    cudaGetSymbolAddress((void**)&p_ulsh,  g_ulsh);
    cudaGetSymbolAddress((void**)&p_ulsl,  g_ulsl);
    cudaGetSymbolAddress((void**)&p_bcvh,  g_bcvh);
    cudaGetSymbolAddress((void**)&p_bcvl,  g_bcvl);

    const int DSM = 98304;
    const int DSW = 147456;
    const int ASM = 49152*2 + 900*4;
    cudaFuncSetAttribute(hgemmW<true, EQKVt>, cudaFuncAttributeMaxDynamicSharedMemorySize, DSW);
    cudaFuncSetAttribute(hgemmOW,       cudaFuncAttributeMaxDynamicSharedMemorySize, DSW);
    cudaFuncSetAttribute(hgemmA<ESQ>,   cudaFuncAttributeMaxDynamicSharedMemorySize, DSM);
    cudaFuncSetAttribute(hgemmA<EY2h>,  cudaFuncAttributeMaxDynamicSharedMemorySize, DSM);
    cudaFuncSetAttribute(hgemmC,        cudaFuncAttributeMaxDynamicSharedMemorySize, DSM);
    cudaFuncSetAttribute(attn_mma,      cudaFuncAttributeMaxDynamicSharedMemorySize, ASM);

    zero_small<<<4, 256>>>();                                              // 0
    prep_bw<<<768, 256>>>(w_qkv, p_bqh, p_bql, 768*256);                   // 1
    xsplit<<<4096, 256>>>(x);                                              // 2
    hgemmW<true, EQKVt><<<dim3(3, 1024), 256, DSW>>>(p_xh, p_xl, p_bqh, p_bql, 8, EQKVt{b_qkv}); // 3

    sum_gnw<<<1, 256>>>(gn_w);
    sru_elem<<<65536, 256>>>(gn_w, gn_b);

    prep_bsq<<<128, 256>>>(sq1, sq2);
    hgemmA<ESQ><<<dim3(1, 1024), 256, DSM>>>(p_kh, p_kl, 256, p_bsqh, p_bsql, 256, 8, ESQ{});
    prep_bcv<<<(2*128*352 + 255)/256, 256>>>(gwc, pwc1);
    hgemmC<<<dim3(1, 1024, 2), 256, DSM>>>(p_bcvh, p_bcvl, gwc_b);
    prep_bp2<<<64, 256>>>(pwc2);
    hgemmA<EY2h><<<dim3(2, 1024), 256, DSM>>>(p_ulsh, p_ulsl, 64, p_bp2h, p_bp2l, 64, 2, EY2h{});

    softmax512<<<2, 512>>>();

    attn_mma<<<dim3(1024, 2, 2), 128, ASM>>>(rel_pos);
    prep_bw<<<256, 256>>>(w_out, p_bouth, p_boutl, 256*256);
    hgemmOW<<<dim3(1, 1024), 256, DSW>>>(p_atth, p_attl, p_bouth, p_boutl, b_out, out);
}